// round 13
// baseline (speedup 1.0000x reference)
#include <cuda_runtime.h>
#include <cuda_fp16.h>

// WordHashing: sparse [B=16384 x 30000] (COO, rows sorted) @ W [30000 x 300] + bias, ReLU.
// R12 post-mortem: spmm frozen at ~30us across all configs; no surfaced pipe
// saturated. Hypothesis: 10x F2F.F32.F16 per nnz on a quarter-rate convert pipe
// (~58% of kernel cycles) is the hidden limiter. R13: process nnz in PAIRS with
// fp16 pre-accumulation (hmul2+hfma2, full-rate fma pipe), halving F2F to 5/nnz;
// f32x2 accumulate via add.rn.f32x2. Values staged as duplicated half2.

#define OUT_DIM   300
#define IN_DIM    30000
#define ROW_INT4  38           // 38 x 16B = 608B per padded fp16 row (304 halves)
#define ROW_BYTES 608
#define MAX_BATCH 16384

#define CONV_THREADS 256
#define CONV_BLOCKS  ((IN_DIM * ROW_INT4 + CONV_THREADS - 1) / CONV_THREADS)

__device__ int g_row_start[MAX_BATCH + 1];
__device__ __align__(128) int4 g_Wh4[IN_DIM * ROW_INT4];   // 18.2 MB fp16 staged weights

// ---------------------------------------------------------------------------
// Fused prep: blocks [0, CONV_BLOCKS) convert W f32 -> padded f16 rows;
// remaining blocks build row_start from sorted sp_rows.
__global__ void prep_kernel(const float* __restrict__ W,
                            const int* __restrict__ rows,
                            int nnz, int batch, int conv_blocks_thr) {
    if (blockIdx.x < (unsigned)conv_blocks_thr) {
        const int i = blockIdx.x * CONV_THREADS + threadIdx.x;
        if (i >= IN_DIM * ROW_INT4) return;
        const int row = i / ROW_INT4;
        const int k   = i - row * ROW_INT4;
        const int col = k * 8;

        float4 a = make_float4(0.f, 0.f, 0.f, 0.f);
        float4 b = make_float4(0.f, 0.f, 0.f, 0.f);
        const float4* src = reinterpret_cast<const float4*>(W + (size_t)row * OUT_DIM + col);
        if (col + 8 <= OUT_DIM)      { a = __ldg(src); b = __ldg(src + 1); }
        else if (col < OUT_DIM)      { a = __ldg(src); }   // k==37: cols 296..299

        __align__(16) __half2 hh[4];
        hh[0] = __floats2half2_rn(a.x, a.y);
        hh[1] = __floats2half2_rn(a.z, a.w);
        hh[2] = __floats2half2_rn(b.x, b.y);
        hh[3] = __floats2half2_rn(b.z, b.w);
        g_Wh4[i] = *reinterpret_cast<const int4*>(hh);
    } else {
        const int i = (blockIdx.x - conv_blocks_thr) * CONV_THREADS + threadIdx.x;
        if (i >= nnz) return;
        int r  = rows[i];
        int rp = (i == 0) ? -1 : rows[i - 1];
        for (int q = rp + 1; q <= r; ++q) g_row_start[q] = i;
        if (i == nnz - 1) {
            for (int q = r + 1; q <= batch; ++q) g_row_start[q] = nnz;
        }
    }
}

// ---------------------------------------------------------------------------
// Paired slot update: acc(f32x2) += f32(w0*v0 + w1*v1) computed in fp16.
// 1 HMUL2 + 1 HFMA2 (full-rate fma pipe) + 2 F2F + 1 ADD.f32x2.
__device__ __forceinline__ void pair_slot(unsigned long long& acc,
                                          unsigned int w0, unsigned int w1,
                                          unsigned int vv0, unsigned int vv1) {
    const __half2 h0  = *reinterpret_cast<const __half2*>(&w0);
    const __half2 h1  = *reinterpret_cast<const __half2*>(&w1);
    const __half2 va  = *reinterpret_cast<const __half2*>(&vv0);
    const __half2 vb  = *reinterpret_cast<const __half2*>(&vv1);
    const __half2 t   = __hfma2(h0, va, __hmul2(h1, vb));
    const float2  f   = __half22float2(t);               // 2x F2F (selector form)
    asm("{\n\t"
        ".reg .b64 fp;\n\t"
        "mov.b64 fp, {%1, %2};\n\t"
        "add.rn.f32x2 %0, %0, fp;\n\t"
        "}" : "+l"(acc) : "f"(f.x), "f"(f.y));
}

// Single-nnz fallback (odd remainder): acc(f32x2) += cvt(w2) * {v,v}.
__device__ __forceinline__ void cvt_fma2(unsigned long long& acc,
                                         unsigned int w2,
                                         unsigned long long vv) {
    __half2 h;
    *reinterpret_cast<unsigned int*>(&h) = w2;
    const float2 wf = __half22float2(h);
    asm("{\n\t"
        ".reg .b64 wp;\n\t"
        "mov.b64 wp, {%1, %2};\n\t"
        "fma.rn.f32x2 %0, wp, %3, %0;\n\t"
        "}" : "+l"(acc) : "f"(wf.x), "f"(wf.y), "l"(vv));
}

// ---------------------------------------------------------------------------
// spmm: 64-thread CTA = 2 warps, one sparse row each (R12 config).
// Lane t owns cols [8t,8t+8) (LDG.128); lanes 0..21 also own cols [256+2t,+2).
// Chunks staged as int2 {c*608, half2(v,v)}, register-prefetched.
__global__ __launch_bounds__(64) void spmm_row_kernel(
    const int*   __restrict__ cols,
    const float* __restrict__ vals,
    const float* __restrict__ bias,
    float*       __restrict__ out,
    int batch)
{
    __shared__ int2 s_cv[2][2][32];
    const int warp = threadIdx.x >> 5;
    const int lane = threadIdx.x & 31;
    const int row  = blockIdx.x * 2 + warp;
    if (row >= batch) return;

    const int start = g_row_start[row];        // uniform -> broadcast LDG
    const int end   = g_row_start[row + 1];

    unsigned long long a0 = 0ull, a1 = 0ull, a2 = 0ull, a3 = 0ull, a4 = 0ull;

    const char* __restrict__ lbase =
        reinterpret_cast<const char*>(g_Wh4) + lane * 16;
    const int tail_imm = 512 - lane * 16 + lane * 4;   // rowp+512+4*lane rel. to lbase
    const bool has_tail = (lane < 22);

    // Prefetch chunk 0: {offset, half2(v,v)}.
    int2 pf = make_int2(0, 0);
    if (start + lane < end) {
        const __half2 hv = __half2half2(__float2half_rn(__ldg(vals + start + lane)));
        pf = make_int2(__ldg(cols + start + lane) * ROW_BYTES,
                       *reinterpret_cast<const int*>(&hv));
    }

    int parity = 0;
    for (int base = start; base < end; base += 32, parity ^= 1) {
        const int rem = end - base;
        const int n   = rem < 32 ? rem : 32;
        s_cv[warp][parity][lane] = pf;         // publish current chunk
        __syncwarp();
        const int nb = base + 32;
        if (nb + lane < end) {                 // prefetch next chunk
            const __half2 hv = __half2half2(__float2half_rn(__ldg(vals + nb + lane)));
            pf = make_int2(__ldg(cols + nb + lane) * ROW_BYTES,
                           *reinterpret_cast<const int*>(&hv));
        }
        #pragma unroll 4
        for (int j = 0; j + 2 <= n; j += 2) {  // paired: 2 gathers in flight
            const int2 cv0 = s_cv[warp][parity][j];
            const int2 cv1 = s_cv[warp][parity][j + 1];
            const char* p0 = lbase + cv0.x;
            const char* p1 = lbase + cv1.x;
            const int4 w40 = __ldg(reinterpret_cast<const int4*>(p0));
            const int4 w41 = __ldg(reinterpret_cast<const int4*>(p1));
            int w10 = 0, w11 = 0;
            if (has_tail) {
                w10 = __ldg(reinterpret_cast<const int*>(p0 + tail_imm));
                w11 = __ldg(reinterpret_cast<const int*>(p1 + tail_imm));
            }
            const unsigned vv0 = (unsigned)cv0.y;
            const unsigned vv1 = (unsigned)cv1.y;
            pair_slot(a0, (unsigned)w40.x, (unsigned)w41.x, vv0, vv1);
            pair_slot(a1, (unsigned)w40.y, (unsigned)w41.y, vv0, vv1);
            pair_slot(a2, (unsigned)w40.z, (unsigned)w41.z, vv0, vv1);
            pair_slot(a3, (unsigned)w40.w, (unsigned)w41.w, vv0, vv1);
            pair_slot(a4, (unsigned)w10,   (unsigned)w11,   vv0, vv1);
        }
        if (n & 1) {                           // odd remainder: single path
            const int2 cv = s_cv[warp][parity][n - 1];
            __half2 hv;
            *reinterpret_cast<int*>(&hv) = cv.y;
            const float v = __low2float(hv);
            unsigned long long vv;
            asm("mov.b64 %0, {%1, %1};" : "=l"(vv) : "f"(v));
            const char* p = lbase + cv.x;
            const int4 w4 = __ldg(reinterpret_cast<const int4*>(p));
            int w1 = 0;
            if (has_tail) w1 = __ldg(reinterpret_cast<const int*>(p + tail_imm));
            cvt_fma2(a0, (unsigned)w4.x, vv);
            cvt_fma2(a1, (unsigned)w4.y, vv);
            cvt_fma2(a2, (unsigned)w4.z, vv);
            cvt_fma2(a3, (unsigned)w4.w, vv);
            cvt_fma2(a4, (unsigned)w1,   vv);
        }
    }

    float acc[10];
    asm("mov.b64 {%0, %1}, %2;" : "=f"(acc[0]), "=f"(acc[1]) : "l"(a0));
    asm("mov.b64 {%0, %1}, %2;" : "=f"(acc[2]), "=f"(acc[3]) : "l"(a1));
    asm("mov.b64 {%0, %1}, %2;" : "=f"(acc[4]), "=f"(acc[5]) : "l"(a2));
    asm("mov.b64 {%0, %1}, %2;" : "=f"(acc[6]), "=f"(acc[7]) : "l"(a3));
    asm("mov.b64 {%0, %1}, %2;" : "=f"(acc[8]), "=f"(acc[9]) : "l"(a4));

    // Epilogue: +bias, ReLU, coalesced stores.
    float* orow = out + (size_t)row * OUT_DIM;
    const int c0 = lane * 8;                   // 0..248
    const float4 b0 = __ldg(reinterpret_cast<const float4*>(bias + c0));
    const float4 b1 = __ldg(reinterpret_cast<const float4*>(bias + c0 + 4));
    float4 o0, o1;
    o0.x = fmaxf(acc[0] + b0.x, 0.f);  o0.y = fmaxf(acc[1] + b0.y, 0.f);
    o0.z = fmaxf(acc[2] + b0.z, 0.f);  o0.w = fmaxf(acc[3] + b0.w, 0.f);
    o1.x = fmaxf(acc[4] + b1.x, 0.f);  o1.y = fmaxf(acc[5] + b1.y, 0.f);
    o1.z = fmaxf(acc[6] + b1.z, 0.f);  o1.w = fmaxf(acc[7] + b1.w, 0.f);
    *reinterpret_cast<float4*>(orow + c0)     = o0;
    *reinterpret_cast<float4*>(orow + c0 + 4) = o1;

    const int c1 = 256 + 2 * lane;             // tail cols; valid while < 300
    if (c1 < OUT_DIM) {                        // lanes 0..21
        const float2 b2 = __ldg(reinterpret_cast<const float2*>(bias + c1));
        float2 o2;
        o2.x = fmaxf(acc[8] + b2.x, 0.f);
        o2.y = fmaxf(acc[9] + b2.y, 0.f);
        *reinterpret_cast<float2*>(orow + c1) = o2;
    }
}

extern "C" void kernel_launch(void* const* d_in, const int* in_sizes, int n_in,
                              void* d_out, int out_size) {
    const int*   sp_rows = (const int*)  d_in[0];
    const int*   sp_cols = (const int*)  d_in[1];
    const float* sp_vals = (const float*)d_in[2];
    const float* weights = (const float*)d_in[3];
    const float* bias    = (const float*)d_in[4];

    const int nnz   = in_sizes[0];
    const int batch = out_size / OUT_DIM;

    const int build_blocks = (nnz + CONV_THREADS - 1) / CONV_THREADS;
    prep_kernel<<<CONV_BLOCKS + build_blocks, CONV_THREADS>>>(
        weights, sp_rows, nnz, batch, CONV_BLOCKS);
    spmm_row_kernel<<<(batch + 1) / 2, 64>>>(sp_cols, sp_vals, bias,
                                             (float*)d_out, batch);
}